// round 11
// baseline (speedup 1.0000x reference)
#include <cuda_runtime.h>
#include <math.h>
#include <stdint.h>

#define NB    2
#define DIM   256
#define NLEN  4096
#define NH    4

// ---------------- scratch (allocation-free: device globals) ----------------
__device__ float g_q[NB * DIM * NLEN];    // [b][h][n][d-paired] tf32, pre-scaled
__device__ float g_k[NB * DIM * NLEN];    // [b][h][m][d-paired] tf32
__device__ float g_v[NB * DIM * NLEN];    // [b][c][m-paired] tf32 (c = dh*NH+h)
__device__ float g_attn[NB * DIM * NLEN]; // [b][c][n] tf32-rounded
__device__ float g_h[NB * 2 * DIM * NLEN];
__device__ float g_scale[2 * DIM];
__device__ float g_shift[2 * DIM];
__device__ float g_bfused[512];
__device__ float g_wr[655360];            // rna-rounded weights
#define WR_Q  0
#define WR_K  65536
#define WR_V  131072
#define WR_1  262144   // Wcat [512][512]: rows 0-255 = rna(W1 top), 256-511 = Wf
#define WR_2  524288

// ======================= helpers ======================
__device__ __forceinline__ uint32_t smem_u32(const void* p) {
    uint32_t a;
    asm("{ .reg .u64 t; cvta.to.shared.u64 t, %1; cvt.u32.u64 %0, t; }"
        : "=r"(a) : "l"(p));
    return a;
}

#define CP_ASYNC16(smaddr, gptr) \
    asm volatile("cp.async.ca.shared.global [%0], [%1], 16;" \
                 :: "r"(smaddr), "l"(gptr) : "memory")
#define CP_COMMIT() asm volatile("cp.async.commit_group;" ::: "memory")
#define CP_WAIT0()  asm volatile("cp.async.wait_group 0;" ::: "memory")

__device__ __forceinline__ float f2tf32f(float x) {
    uint32_t u;
    asm("cvt.rna.tf32.f32 %0, %1;" : "=r"(u) : "f"(x));
    return __uint_as_float(u);
}
__device__ __forceinline__ int perm8(int p) { return (p < 4) ? 2 * p : 2 * (p - 4) + 1; }

// D += A @ B : m16n8k8 tf32; A row-major, B col-major, C fp32
__device__ __forceinline__ void mma8(float* c, const uint32_t* a,
                                     uint32_t b0, uint32_t b1) {
    asm volatile(
        "mma.sync.aligned.m16n8k8.row.col.f32.tf32.tf32.f32 "
        "{%0,%1,%2,%3}, {%4,%5,%6,%7}, {%8,%9}, {%0,%1,%2,%3};"
        : "+f"(c[0]), "+f"(c[1]), "+f"(c[2]), "+f"(c[3])
        : "r"(a[0]), "r"(a[1]), "r"(a[2]), "r"(a[3]), "r"(b0), "r"(b1));
}

// ---------------------------------------------------------------------------
// One-shot weight rounding to tf32 (rna). W1: only top 256 rows (Wcat top).
// ---------------------------------------------------------------------------
__global__ __launch_bounds__(256) void round_weights(
    const float* __restrict__ wq, const float* __restrict__ wk,
    const float* __restrict__ wv, const float* __restrict__ w1,
    const float* __restrict__ w2, float* __restrict__ dst)
{
    int i = blockIdx.x * 256 + threadIdx.x;
    if      (i < 65536)  dst[WR_Q + i] = f2tf32f(wq[i]);
    else if (i < 131072) dst[WR_K + i - 65536]  = f2tf32f(wk[i - 65536]);
    else if (i < 196608) dst[WR_V + i - 131072] = f2tf32f(wv[i - 131072]);
    else if (i < 327680) dst[WR_1 + i - 196608] = f2tf32f(w1[i - 196608]);
    else if (i < 458752) dst[WR_2 + i - 327680] = f2tf32f(w2[i - 327680]);
}

// ---------------------------------------------------------------------------
// Wf[c][o] = sum_j Wo[c][j] * W1[256+j][o]  (fp32 accumulate, rna at write).
// grid (8 o-tiles, 4 c-tiles), 64x64 tiles, BK=16, SIMT.
// ---------------------------------------------------------------------------
__global__ __launch_bounds__(256) void fuse_w1(
    const float* __restrict__ Wo, const float* __restrict__ W1,
    float* __restrict__ dst)   // dst = wr + WR_1 + 131072 (Wcat bottom)
{
    __shared__ float As[16][68];   // As[j][c]
    __shared__ float Bs[16][68];   // Bs[j][o]
    const int c0 = blockIdx.y * 64, o0 = blockIdx.x * 64;
    const int tid = threadIdx.x, ty = tid >> 4, tx = tid & 15;
    float acc[4][4] = {};
    for (int k0 = 0; k0 < 256; k0 += 16) {
        __syncthreads();
        {   // A: Wo rows (coalesced along j), scatter-transpose into As
            int cc = tid >> 2, j4 = (tid & 3) * 4;
            float4 a = *(const float4*)&Wo[(size_t)(c0 + cc) * 256 + k0 + j4];
            As[j4 + 0][cc] = a.x; As[j4 + 1][cc] = a.y;
            As[j4 + 2][cc] = a.z; As[j4 + 3][cc] = a.w;
        }
        {   // B: W1 bottom rows, coalesced
            int col = tid & 63, jr = tid >> 6;
            #pragma unroll
            for (int jj = jr; jj < 16; jj += 4)
                Bs[jj][col] = W1[(size_t)(256 + k0 + jj) * 512 + o0 + col];
        }
        __syncthreads();
        #pragma unroll
        for (int kk = 0; kk < 16; kk++) {
            float av[4], bv[4];
            #pragma unroll
            for (int i = 0; i < 4; i++) av[i] = As[kk][ty * 4 + i];
            #pragma unroll
            for (int j = 0; j < 4; j++) bv[j] = Bs[kk][tx * 4 + j];
            #pragma unroll
            for (int i = 0; i < 4; i++)
                #pragma unroll
                for (int j = 0; j < 4; j++)
                    acc[i][j] = fmaf(av[i], bv[j], acc[i][j]);
        }
    }
    #pragma unroll
    for (int i = 0; i < 4; i++)
        #pragma unroll
        for (int j = 0; j < 4; j++)
            dst[(size_t)(c0 + ty * 4 + i) * 512 + o0 + tx * 4 + j] =
                f2tf32f(acc[i][j]);
}

// bfused[o] = b1[o] + sum_j bo[j] * W1[256+j][o]
__global__ __launch_bounds__(256) void bias_fuse(
    const float* __restrict__ bo, const float* __restrict__ W1,
    const float* __restrict__ b1, float* __restrict__ bf)
{
    int o = blockIdx.x * 256 + threadIdx.x;
    float s = b1[o];
    for (int j = 0; j < 256; j++)
        s = fmaf(bo[j], W1[(size_t)(256 + j) * 512 + o], s);
    bf[o] = s;
}

// ===========================================================================
// Shared GEMM machinery: 128x128 CTA tile, BK=32, double-buffered cp.async,
// 8 warps (4m x 2n), warp tile 32m x 64n, mma.m16n8k8 tf32.
// ===========================================================================
#define GEMM_SMEM (17408 * 4)

#define GEMM_COMPUTE_STAGE(AsP, BsP)                                           \
    _Pragma("unroll")                                                          \
    for (int kc = 0; kc < 4; kc++) {                                           \
        uint32_t af[2][4];                                                     \
        _Pragma("unroll")                                                      \
        for (int f = 0; f < 2; f++) {                                          \
            int mr = wm * 32 + f * 16 + gid;                                   \
            af[f][0] = __float_as_uint(AsP[(kc * 8 + tig) * 136 + mr]);        \
            af[f][1] = __float_as_uint(AsP[(kc * 8 + tig) * 136 + mr + 8]);    \
            af[f][2] = __float_as_uint(AsP[(kc * 8 + tig + 4) * 136 + mr]);    \
            af[f][3] = __float_as_uint(AsP[(kc * 8 + tig + 4) * 136 + mr + 8]);\
        }                                                                      \
        _Pragma("unroll")                                                      \
        for (int j = 0; j < 8; j++) {                                          \
            int nc = wn * 64 + j * 8 + gid;                                    \
            uint32_t b0 = __float_as_uint(BsP[(kc * 8 + tig) * 136 + nc]);     \
            uint32_t b1 = __float_as_uint(BsP[(kc * 8 + tig + 4) * 136 + nc]); \
            mma8(acc[0][j], af[0], b0, b1);                                    \
            mma8(acc[1][j], af[1], b0, b1);                                    \
        }                                                                      \
    }

// ---------------------------------------------------------------------------
// Fused Q/K/V projection: grid (64, 2, 3); x folds (b, n-tile); z = mat.
// ---------------------------------------------------------------------------
__global__ __launch_bounds__(256) void gemm_qkv(
    const float* __restrict__ wr,
    const float* __restrict__ bq, const float* __restrict__ bk,
    const float* __restrict__ bv,
    const float* __restrict__ x, const float* __restrict__ src,
    float* __restrict__ qo, float* __restrict__ ko, float* __restrict__ vo)
{
    extern __shared__ float dsm[];
    float* As = dsm;
    float* Bs = dsm + 8704;
    const int mat = blockIdx.z;
    const int ng = blockIdx.x * 128;
    const int b = ng >> 12, n0 = ng & (NLEN - 1);
    const float* W    = wr + mat * 65536;
    const float* bias = (mat == 0) ? bq : (mat == 1) ? bk : bv;
    const float* in   = (mat == 0) ? x : src;
    const int m0 = blockIdx.y * 128;
    const int tid = threadIdx.x, wid = tid >> 5, lane = tid & 31;
    const int gid = lane >> 2, tig = lane & 3;
    const int wm = wid & 3, wn = wid >> 2;
    const uint32_t sA = smem_u32(As), sB = smem_u32(Bs);
    const int r0 = tid >> 5, c0 = (tid & 31) * 4;

    auto load_async = [&](int buf, int k0) {
        #pragma unroll
        for (int p = 0; p < 4; p++) {
            int r = r0 + p * 8;
            CP_ASYNC16(sA + (buf * 4352 + r * 136 + c0) * 4,
                       &W[(size_t)(k0 + r) * 256 + m0 + c0]);
            CP_ASYNC16(sB + (buf * 4352 + r * 136 + c0) * 4,
                       &in[((size_t)b * 256 + k0 + r) * NLEN + n0 + c0]);
        }
        CP_COMMIT();
    };

    load_async(0, 0);
    CP_WAIT0();
    __syncthreads();

    float acc[2][8][4] = {};
    for (int s = 0; s < 8; s++) {
        const int cur = s & 1, nxt = cur ^ 1;
        if (s + 1 < 8) load_async(nxt, (s + 1) * 32);
        const float* AsP = As + cur * 4352;
        const float* BsP = Bs + cur * 4352;
        GEMM_COMPUTE_STAGE(AsP, BsP)
        CP_WAIT0();
        __syncthreads();
    }

    const float scl = (mat == 0) ? 0.125f : 1.0f;
    #pragma unroll
    for (int f = 0; f < 2; f++)
        #pragma unroll
        for (int j = 0; j < 8; j++) {
            int m_lo = m0 + wm * 32 + f * 16 + gid;
            int m_hi = m_lo + 8;
            int n = n0 + wn * 64 + j * 8 + 2 * tig;
            float blo = bias[m_lo], bhi = bias[m_hi];
            float v00 = acc[f][j][0] + blo, v01 = acc[f][j][1] + blo;
            float v10 = acc[f][j][2] + bhi, v11 = acc[f][j][3] + bhi;
            if (mat < 2) {
                float* out = (mat == 0) ? qo : ko;
                v00 *= scl; v01 *= scl; v10 *= scl; v11 *= scl;
                int dl = m_lo >> 2, hl = m_lo & 3;
                int dh2 = m_hi >> 2, hh2 = m_hi & 3;
                int dlp = (dl & ~7) | perm8(dl & 7);
                int dhp = (dh2 & ~7) | perm8(dh2 & 7);
                float* ol = out + (((size_t)b * NH + hl) * NLEN) * 64;
                float* oh = out + (((size_t)b * NH + hh2) * NLEN) * 64;
                ol[(size_t)(n)     * 64 + dlp] = f2tf32f(v00);
                ol[(size_t)(n + 1) * 64 + dlp] = f2tf32f(v01);
                oh[(size_t)(n)     * 64 + dhp] = f2tf32f(v10);
                oh[(size_t)(n + 1) * 64 + dhp] = f2tf32f(v11);
            } else {
                int na  = (n & ~7) | perm8(n & 7);
                int nb2 = ((n + 1) & ~7) | perm8((n + 1) & 7);
                float* ob = vo + (size_t)b * 256 * NLEN;
                ob[(size_t)m_lo * NLEN + na]  = f2tf32f(v00);
                ob[(size_t)m_lo * NLEN + nb2] = f2tf32f(v01);
                ob[(size_t)m_hi * NLEN + na]  = f2tf32f(v10);
                ob[(size_t)m_hi * NLEN + nb2] = f2tf32f(v11);
            }
        }
}

// ---------------------------------------------------------------------------
// cat GEMM: h = Wcat @ concat(x, attn) + bfused. K=512, M=512. grid (64, 4).
// ---------------------------------------------------------------------------
__global__ __launch_bounds__(256) void gemm_cat_tc(
    const float* __restrict__ W, const float* __restrict__ bias,
    const float* __restrict__ x, const float* __restrict__ attn,
    float* __restrict__ out)
{
    extern __shared__ float dsm[];
    float* As = dsm;
    float* Bs = dsm + 8704;
    const int ng = blockIdx.x * 128;
    const int b = ng >> 12, n0 = ng & (NLEN - 1);
    const int m0 = blockIdx.y * 128;
    const int tid = threadIdx.x, wid = tid >> 5, lane = tid & 31;
    const int gid = lane >> 2, tig = lane & 3;
    const int wm = wid & 3, wn = wid >> 2;
    const uint32_t sA = smem_u32(As), sB = smem_u32(Bs);
    const int r0 = tid >> 5, c0 = (tid & 31) * 4;

    auto load_async = [&](int buf, int k0) {
        #pragma unroll
        for (int p = 0; p < 4; p++) {
            int r = r0 + p * 8;
            CP_ASYNC16(sA + (buf * 4352 + r * 136 + c0) * 4,
                       &W[(size_t)(k0 + r) * 512 + m0 + c0]);
            const float* src = (k0 < 256)
                ? x    + ((size_t)b * 256 + k0 + r) * NLEN
                : attn + ((size_t)b * 256 + (k0 - 256) + r) * NLEN;
            CP_ASYNC16(sB + (buf * 4352 + r * 136 + c0) * 4, src + n0 + c0);
        }
        CP_COMMIT();
    };

    load_async(0, 0);
    CP_WAIT0();
    __syncthreads();

    float acc[2][8][4] = {};
    for (int s = 0; s < 16; s++) {
        const int cur = s & 1, nxt = cur ^ 1;
        if (s + 1 < 16) load_async(nxt, (s + 1) * 32);
        const float* AsP = As + cur * 4352;
        const float* BsP = Bs + cur * 4352;
        GEMM_COMPUTE_STAGE(AsP, BsP)
        CP_WAIT0();
        __syncthreads();
    }

    #pragma unroll
    for (int f = 0; f < 2; f++)
        #pragma unroll
        for (int j = 0; j < 8; j++) {
            int m_lo = m0 + wm * 32 + f * 16 + gid;
            int m_hi = m_lo + 8;
            int n = n0 + wn * 64 + j * 8 + 2 * tig;
            float blo = bias[m_lo], bhi = bias[m_hi];
            float* ob = out + (size_t)b * 512 * NLEN;
            *(float2*)&ob[(size_t)m_lo * NLEN + n] =
                make_float2(acc[f][j][0] + blo, acc[f][j][1] + blo);
            *(float2*)&ob[(size_t)m_hi * NLEN + n] =
                make_float2(acc[f][j][2] + bhi, acc[f][j][3] + bhi);
        }
}

// ---------------------------------------------------------------------------
// bn GEMM, 64-wide N tiles: out = W2 @ relu(h*scale+shift) + b2.
// K=512, M=256. grid (128, 2). 8 warps (4m x 2n), warp tile 32m x 32n.
// smem: As 2x(32x136)=8704 fl, Bs 2x(32x72)=4608 fl -> 53248 B.
// ---------------------------------------------------------------------------
#define BN64_SMEM (13312 * 4)
__global__ __launch_bounds__(256) void gemm_bn64(
    const float* __restrict__ W, const float* __restrict__ bias,
    const float* __restrict__ hbuf,
    const float* __restrict__ scale, const float* __restrict__ shift,
    float* __restrict__ out)
{
    extern __shared__ float dsm[];
    float* As = dsm;
    float* Bs = dsm + 8704;
    const int ng = blockIdx.x * 64;
    const int b = ng >> 12, n0 = ng & (NLEN - 1);
    const int m0 = blockIdx.y * 128;
    const int tid = threadIdx.x, wid = tid >> 5, lane = tid & 31;
    const int gid = lane >> 2, tig = lane & 3;
    const int wm = wid & 3, wn = wid >> 2;
    const uint32_t sA = smem_u32(As);
    const int r0 = tid >> 5, c0 = (tid & 31) * 4;       // A loader
    const int r0b = tid >> 4, c0b = (tid & 15) * 4;     // B loader (64-wide)

    float4 br[2];
    float  bsc[2], bsh[2];

    auto load_a = [&](int buf, int k0) {
        #pragma unroll
        for (int p = 0; p < 4; p++) {
            int r = r0 + p * 8;
            CP_ASYNC16(sA + (buf * 4352 + r * 136 + c0) * 4,
                       &W[(size_t)(k0 + r) * 256 + m0 + c0]);
        }
        CP_COMMIT();
    };
    auto load_b_regs = [&](int k0) {
        #pragma unroll
        for (int p = 0; p < 2; p++) {
            int r = r0b + p * 16;
            br[p] = *(const float4*)&hbuf[((size_t)b * 512 + k0 + r) * NLEN + n0 + c0b];
            bsc[p] = scale[k0 + r];
            bsh[p] = shift[k0 + r];
        }
    };
    auto sts_b = [&](int buf) {
        #pragma unroll
        for (int p = 0; p < 2; p++) {
            int r = r0b + p * 16;
            float4 v = br[p];
            v.x = f2tf32f(fmaxf(fmaf(v.x, bsc[p], bsh[p]), 0.0f));
            v.y = f2tf32f(fmaxf(fmaf(v.y, bsc[p], bsh[p]), 0.0f));
            v.z = f2tf32f(fmaxf(fmaf(v.z, bsc[p], bsh[p]), 0.0f));
            v.w = f2tf32f(fmaxf(fmaf(v.w, bsc[p], bsh[p]), 0.0f));
            *(float4*)&Bs[buf * 2304 + r * 72 + c0b] = v;
        }
    };

    load_b_regs(0);
    load_a(0, 0);
    CP_WAIT0();
    sts_b(0);
    __syncthreads();

    float acc[2][4][4] = {};
    for (int s = 0; s < 16; s++) {
        const int cur = s & 1, nxt = cur ^ 1;
        if (s + 1 < 16) {
            load_a(nxt, (s + 1) * 32);
            load_b_regs((s + 1) * 32);
        }
        const float* AsP = As + cur * 4352;
        const float* BsP = Bs + cur * 2304;
        #pragma unroll
        for (int kc = 0; kc < 4; kc++) {
            uint32_t af[2][4];
            #pragma unroll
            for (int f = 0; f < 2; f++) {
                int mr = wm * 32 + f * 16 + gid;
                af[f][0] = __float_as_uint(AsP[(kc * 8 + tig) * 136 + mr]);
                af[f][1] = __float_as_uint(AsP[(kc * 8 + tig) * 136 + mr + 8]);
                af[f][2] = __float_as_uint(AsP[(kc * 8 + tig + 4) * 136 + mr]);
                af[f][3] = __float_as_uint(AsP[(kc * 8 + tig + 4) * 136 + mr + 8]);
            }
            #pragma unroll
            for (int j = 0; j < 4; j++) {
                int nc = wn * 32 + j * 8 + gid;
                uint32_t b0 = __float_as_uint(BsP[(kc * 8 + tig) * 72 + nc]);
                uint32_t b1 = __float_as_uint(BsP[(kc * 8 + tig + 4) * 72 + nc]);
                mma8(acc[0][j], af[0], b0, b1);
                mma8(acc[1][j], af[1], b0, b1);
            }
        }
        if (s + 1 < 16) sts_b(nxt);
        CP_WAIT0();
        __syncthreads();
    }

    #pragma unroll
    for (int f = 0; f < 2; f++)
        #pragma unroll
        for (int j = 0; j < 4; j++) {
            int m_lo = m0 + wm * 32 + f * 16 + gid;
            int m_hi = m_lo + 8;
            int n = n0 + wn * 32 + j * 8 + 2 * tig;
            float blo = bias[m_lo], bhi = bias[m_hi];
            float* ob = out + (size_t)b * 256 * NLEN;
            *(float2*)&ob[(size_t)m_lo * NLEN + n] =
                make_float2(acc[f][j][0] + blo, acc[f][j][1] + blo);
            *(float2*)&ob[(size_t)m_hi * NLEN + n] =
                make_float2(acc[f][j][2] + bhi, acc[f][j][3] + bhi);
        }
}

// ---------------------------------------------------------------------------
// BatchNorm (train-mode) batch statistics -> per-channel (scale, shift)
// ---------------------------------------------------------------------------
__global__ __launch_bounds__(256) void bn_stats(
    const float* __restrict__ hbuf,
    const float* __restrict__ gamma, const float* __restrict__ beta,
    float* __restrict__ scale, float* __restrict__ shift)
{
    const int c = blockIdx.x;
    float s = 0.f, ss = 0.f;
    for (int idx = threadIdx.x; idx < NB * NLEN; idx += 256) {
        int b = idx >> 12, n = idx & (NLEN - 1);
        float v = hbuf[((size_t)b * 512 + c) * NLEN + n];
        s += v;
        ss = fmaf(v, v, ss);
    }
    #pragma unroll
    for (int off = 16; off; off >>= 1) {
        s  += __shfl_xor_sync(0xffffffffu, s, off);
        ss += __shfl_xor_sync(0xffffffffu, ss, off);
    }
    __shared__ float rs[8], rss[8];
    int w = threadIdx.x >> 5;
    if ((threadIdx.x & 31) == 0) { rs[w] = s; rss[w] = ss; }
    __syncthreads();
    if (threadIdx.x == 0) {
        float S = 0.f, SS = 0.f;
        #pragma unroll
        for (int i = 0; i < 8; i++) { S += rs[i]; SS += rss[i]; }
        float mean = S * (1.0f / (NB * NLEN));
        float var  = SS * (1.0f / (NB * NLEN)) - mean * mean;
        float rstd = rsqrtf(var + 1e-5f);
        float a = gamma[c] * rstd;
        scale[c] = a;
        shift[c] = beta[c] - mean * a;
    }
}

// ===========================================================================
// tf32 mma.sync flash attention, pitch-72 SMEM (conflict-free float2 LDS).
// ===========================================================================
#define KP 72
#define KS_F 0
#define VS_F 9216
#define PS_F 18432
#define FLASH_SMEM ((18432 + 9216) * 4)   // 110592 B -> 2 CTAs/SM

__global__ __launch_bounds__(256, 2) void flash_mma(
    const float* __restrict__ q2, const float* __restrict__ k2,
    const float* __restrict__ v, float* __restrict__ attn)
{
    extern __shared__ float sm[];
    const uint32_t smb = smem_u32(sm);
    const int tid = threadIdx.x;
    const int wid = tid >> 5, lane = tid & 31;
    const int gid = lane >> 2, tig = lane & 3;
    const int b = blockIdx.z, hh = blockIdx.y;
    const int q0 = blockIdx.x * 128;
    const size_t bh = (size_t)b * NH + hh;
    const float* kbase = k2 + bh * NLEN * 64;
    const float* vbase = v + ((size_t)b * DIM + hh) * NLEN;

    // ---- stage Q (already scaled + tf32); pitch 72
    #pragma unroll
    for (int i = 0; i < 8; i++) {
        int idx = tid + i * 256;
        int r = idx >> 4, c = (idx & 15) * 4;
        *(float4*)&sm[PS_F + r * KP + c] =
            *(const float4*)&q2[(bh * NLEN + q0 + r) * 64 + c];
    }
    __syncthreads();

    const int row0 = wid * 16 + gid, row1 = row0 + 8;
    uint32_t aq[8][4];
    #pragma unroll
    for (int k = 0; k < 8; k++) {
        float2 fa = *(const float2*)&sm[PS_F + row0 * KP + k * 8 + 2 * tig];
        float2 fb = *(const float2*)&sm[PS_F + row1 * KP + k * 8 + 2 * tig];
        aq[k][0] = __float_as_uint(fa.x);
        aq[k][1] = __float_as_uint(fb.x);
        aq[k][2] = __float_as_uint(fa.y);
        aq[k][3] = __float_as_uint(fb.y);
    }
    __syncthreads();

    // ---- prologue: tile 0 -> buffer 0
    {
        #pragma unroll
        for (int i = 0; i < 4; i++) {
            int idx = tid + i * 256;
            int r = idx >> 4, c = (idx & 15) * 4;
            CP_ASYNC16(smb + (KS_F + r * KP + c) * 4, kbase + (size_t)r * 64 + c);
            CP_ASYNC16(smb + (VS_F + r * KP + c) * 4,
                       vbase + (size_t)r * NH * NLEN + c);
        }
        CP_COMMIT();
        CP_WAIT0();
        __syncthreads();
    }

    float o[8][4] = {};
    float l0 = 0.f, l1 = 0.f;
    float* Pw = sm + PS_F + wid * 16 * KP;

    for (int t = 0; t < NLEN / 64; t++) {
        const int bufc = t & 1;
        if (t + 1 < NLEN / 64) {
            const int bn = (t + 1) & 1;
            const int m0 = (t + 1) * 64;
            #pragma unroll
            for (int i = 0; i < 4; i++) {
                int idx = tid + i * 256;
                int r = idx >> 4, c = (idx & 15) * 4;
                CP_ASYNC16(smb + (KS_F + bn * 4608 + r * KP + c) * 4,
                           kbase + (size_t)(m0 + r) * 64 + c);
                CP_ASYNC16(smb + (VS_F + bn * 4608 + r * KP + c) * 4,
                           vbase + (size_t)r * NH * NLEN + m0 + c);
            }
            CP_COMMIT();
        }

        // ---- S = Q @ K^T
        const float* Ks = sm + KS_F + bufc * 4608;
        float s[8][4] = {};
        #pragma unroll
        for (int k = 0; k < 8; k++) {
            #pragma unroll
            for (int j = 0; j < 8; j++) {
                float2 kb = *(const float2*)&Ks[(j * 8 + gid) * KP + k * 8 + 2 * tig];
                mma8(s[j], aq[k], __float_as_uint(kb.x), __float_as_uint(kb.y));
            }
        }

        // ---- softmax; lsum over ROUNDED p
        #pragma unroll
        for (int j = 0; j < 8; j++) {
            float p0 = f2tf32f(__expf(s[j][0]));
            float p1 = f2tf32f(__expf(s[j][1]));
            float p2 = f2tf32f(__expf(s[j][2]));
            float p3 = f2tf32f(__expf(s[j][3]));
            l0 += p0 + p1;
            l1 += p2 + p3;
            *(float2*)&Pw[gid * KP + j * 8 + 2 * tig] = make_float2(p0, p1);
            *(float2*)&Pw[(gid + 8) * KP + j * 8 + 2 * tig] = make_float2(p2, p3);
        }
        __syncwarp();

        // ---- O += P @ V
        const float* Vs = sm + VS_F + bufc * 4608;
        #pragma unroll
        for (int k = 0; k < 8; k++) {
            uint32_t ap[4];
            ap[0] = __float_as_uint(Pw[gid * KP + k * 8 + tig]);
            ap[1] = __float_as_uint(Pw[(gid + 8) * KP + k * 8 + tig]);
            ap[2] = __float_as_uint(Pw[gid * KP + k * 8 + tig + 4]);
            ap[3] = __float_as_uint(Pw[(gid + 8) * KP + k * 8 + tig + 4]);
            #pragma unroll
            for (int j = 0; j < 8; j++) {
                float2 vb = *(const float2*)&Vs[(j * 8 + gid) * KP + k * 8 + 2 * tig];
                mma8(o[j], ap, __float_as_uint(vb.x), __float_as_uint(vb.y));
            }
        }
        __syncwarp();

        CP_WAIT0();
        __syncthreads();
    }

    // ---- finalize
    l0 += __shfl_xor_sync(0xffffffffu, l0, 1);
    l0 += __shfl_xor_sync(0xffffffffu, l0, 2);
    l1 += __shfl_xor_sync(0xffffffffu, l1, 1);
    l1 += __shfl_xor_sync(0xffffffffu, l1, 2);
    const float inv0 = 1.0f / l0, inv1 = 1.0f / l1;
    #pragma unroll
    for (int j = 0; j < 8; j++) {
        o[j][0] *= inv0; o[j][1] *= inv0;
        o[j][2] *= inv1; o[j][3] *= inv1;
    }

    // ---- stage O as [64 d][128 q] (pitch 132), rna-round, coalesced store
    __syncthreads();
    float* stage = sm;
    #pragma unroll
    for (int j = 0; j < 8; j++) {
        int d0 = j * 8 + 2 * tig;
        stage[(d0 + 0) * 132 + row0] = o[j][0];
        stage[(d0 + 1) * 132 + row0] = o[j][1];
        stage[(d0 + 0) * 132 + row1] = o[j][2];
        stage[(d0 + 1) * 132 + row1] = o[j][3];
    }
    __syncthreads();
    #pragma unroll
    for (int i = 0; i < 8; i++) {
        int idx = tid + i * 256;
        int r = idx >> 5, c = (idx & 31) * 4;
        float4 t = *(const float4*)&stage[r * 132 + c];
        t.x = f2tf32f(t.x); t.y = f2tf32f(t.y);
        t.z = f2tf32f(t.z); t.w = f2tf32f(t.w);
        *(float4*)&attn[((size_t)b * DIM + r * NH + hh) * NLEN + q0 + c] = t;
    }
}

// ---------------------------------------------------------------------------
static float* symaddr(const void* sym) {
    void* p = nullptr;
    cudaGetSymbolAddress(&p, sym);
    return (float*)p;
}

extern "C" void kernel_launch(void* const* d_in, const int* in_sizes, int n_in,
                              void* d_out, int out_size)
{
    const float* x      = (const float*)d_in[0];
    const float* source = (const float*)d_in[1];
    const float* Wq = (const float*)d_in[2];
    const float* bq = (const float*)d_in[3];
    const float* Wk = (const float*)d_in[4];
    const float* bk = (const float*)d_in[5];
    const float* Wv = (const float*)d_in[6];
    const float* bv = (const float*)d_in[7];
    const float* Wo = (const float*)d_in[8];
    const float* bo = (const float*)d_in[9];
    const float* W1 = (const float*)d_in[10];
    const float* b1 = (const float*)d_in[11];
    const float* gamma = (const float*)d_in[12];
    const float* beta  = (const float*)d_in[13];
    const float* W2 = (const float*)d_in[14];
    const float* b2 = (const float*)d_in[15];
    float* out = (float*)d_out;

    float* q    = symaddr(g_q);
    float* kbuf = symaddr(g_k);
    float* vbuf = symaddr(g_v);
    float* attn = symaddr(g_attn);
    float* hbuf = symaddr(g_h);
    float* scl  = symaddr(g_scale);
    float* shf  = symaddr(g_shift);
    float* bfu  = symaddr(g_bfused);
    float* wr   = symaddr(g_wr);

    cudaFuncSetAttribute(flash_mma,
                         cudaFuncAttributeMaxDynamicSharedMemorySize, FLASH_SMEM);
    cudaFuncSetAttribute(gemm_qkv,
                         cudaFuncAttributeMaxDynamicSharedMemorySize, GEMM_SMEM);
    cudaFuncSetAttribute(gemm_cat_tc,
                         cudaFuncAttributeMaxDynamicSharedMemorySize, GEMM_SMEM);
    cudaFuncSetAttribute(gemm_bn64,
                         cudaFuncAttributeMaxDynamicSharedMemorySize, BN64_SMEM);

    dim3 blk(256);
    // prep: rounded weights, fused Wcat bottom (W1_bot @ Wo), fused bias
    round_weights<<<1792, blk>>>(Wq, Wk, Wv, W1, W2, wr);
    fuse_w1<<<dim3(8, 4), blk>>>(Wo, W1, wr + WR_1 + 131072);
    bias_fuse<<<2, blk>>>(bo, W1, b1, bfu);
    // fused Q/K/V projections (192 CTAs, one wave)
    gemm_qkv<<<dim3(64, 2, 3), blk, GEMM_SMEM>>>(
        wr, bq, bk, bv, x, source, q, kbuf, vbuf);
    // attention
    flash_mma<<<dim3(32, NH, NB), blk, FLASH_SMEM>>>(q, kbuf, vbuf, attn);
    // h = Wcat @ concat(x, attn) + bfused  (msg GEMM algebraically fused away)
    gemm_cat_tc<<<dim3(64, 4), blk, GEMM_SMEM>>>(
        wr + WR_1, bfu, x, attn, hbuf);
    // batchnorm stats -> per-channel scale/shift
    bn_stats<<<512, blk>>>(hbuf, gamma, beta, scl, shf);
    // final: W2 @ relu(bn(h)) + b2, 64-wide N tiles (256 CTAs)
    gemm_bn64<<<dim3(128, 2), blk, BN64_SMEM>>>(
        wr + WR_2, b2, hbuf, scl, shf, out);
}

// round 13
// speedup vs baseline: 1.0435x; 1.0435x over previous
#include <cuda_runtime.h>
#include <math.h>
#include <stdint.h>

#define NB    2
#define DIM   256
#define NLEN  4096
#define NH    4

// ---------------- scratch (allocation-free: device globals) ----------------
__device__ float g_q[NB * DIM * NLEN];    // [b][h][n][d-paired] tf32, pre-scaled
__device__ float g_k[NB * DIM * NLEN];    // [b][h][m][d-paired] tf32
__device__ float g_v[NB * DIM * NLEN];    // [b][c][m-paired] tf32 (c = dh*NH+h)
__device__ float g_attn[NB * DIM * NLEN]; // [b][c][n] tf32-rounded
__device__ float g_msg[NB * DIM * NLEN];  // tf32-rounded
__device__ float g_h[NB * 2 * DIM * NLEN];
__device__ float g_scale[2 * DIM];
__device__ float g_shift[2 * DIM];
__device__ float g_wr[655360];            // rna-rounded weights
#define WR_Q  0
#define WR_K  65536
#define WR_V  131072
#define WR_O  196608
#define WR_1  262144
#define WR_2  524288

// ======================= helpers ======================
__device__ __forceinline__ uint32_t smem_u32(const void* p) {
    uint32_t a;
    asm("{ .reg .u64 t; cvta.to.shared.u64 t, %1; cvt.u32.u64 %0, t; }"
        : "=r"(a) : "l"(p));
    return a;
}

#define CP_ASYNC16(smaddr, gptr) \
    asm volatile("cp.async.ca.shared.global [%0], [%1], 16;" \
                 :: "r"(smaddr), "l"(gptr) : "memory")
#define CP_COMMIT() asm volatile("cp.async.commit_group;" ::: "memory")
#define CP_WAIT0()  asm volatile("cp.async.wait_group 0;" ::: "memory")
#define CP_WAIT2()  asm volatile("cp.async.wait_group 2;" ::: "memory")

__device__ __forceinline__ float f2tf32f(float x) {
    uint32_t u;
    asm("cvt.rna.tf32.f32 %0, %1;" : "=r"(u) : "f"(x));
    return __uint_as_float(u);
}
__device__ __forceinline__ int perm8(int p) { return (p < 4) ? 2 * p : 2 * (p - 4) + 1; }

// D += A @ B : m16n8k8 tf32; A row-major, B col-major, C fp32
__device__ __forceinline__ void mma8(float* c, const uint32_t* a,
                                     uint32_t b0, uint32_t b1) {
    asm volatile(
        "mma.sync.aligned.m16n8k8.row.col.f32.tf32.tf32.f32 "
        "{%0,%1,%2,%3}, {%4,%5,%6,%7}, {%8,%9}, {%0,%1,%2,%3};"
        : "+f"(c[0]), "+f"(c[1]), "+f"(c[2]), "+f"(c[3])
        : "r"(a[0]), "r"(a[1]), "r"(a[2]), "r"(a[3]), "r"(b0), "r"(b1));
}

// ---------------------------------------------------------------------------
// One-shot weight rounding to tf32 (rna)
// ---------------------------------------------------------------------------
__global__ __launch_bounds__(256) void round_weights(
    const float* __restrict__ wq, const float* __restrict__ wk,
    const float* __restrict__ wv, const float* __restrict__ wo,
    const float* __restrict__ w1, const float* __restrict__ w2,
    float* __restrict__ dst)
{
    int i = blockIdx.x * 256 + threadIdx.x;
    if      (i < 65536)  dst[i] = f2tf32f(wq[i]);
    else if (i < 131072) dst[i] = f2tf32f(wk[i - 65536]);
    else if (i < 196608) dst[i] = f2tf32f(wv[i - 131072]);
    else if (i < 262144) dst[i] = f2tf32f(wo[i - 196608]);
    else if (i < 524288) dst[i] = f2tf32f(w1[i - 262144]);
    else if (i < 655360) dst[i] = f2tf32f(w2[i - 524288]);
}

// ===========================================================================
// GEMM machinery. 128x128 CTA tile, 8 warps (4m x 2n), warp tile 32m x 64n.
// 4-stage cp.async pipeline at BK=16 (qkv/msg/cat) keeps 3 load-groups in
// flight -> ~3 compute-stages of latency slack. SMEM = 8 x 2176 floats.
// ===========================================================================
#define GEMM_SMEM (17408 * 4)

#define GEMM_STAGE16(AsP, BsP)                                                 \
    _Pragma("unroll")                                                          \
    for (int kc = 0; kc < 2; kc++) {                                           \
        uint32_t af[2][4];                                                     \
        _Pragma("unroll")                                                      \
        for (int f = 0; f < 2; f++) {                                          \
            int mr = wm * 32 + f * 16 + gid;                                   \
            af[f][0] = __float_as_uint(AsP[(kc * 8 + tig) * 136 + mr]);        \
            af[f][1] = __float_as_uint(AsP[(kc * 8 + tig) * 136 + mr + 8]);    \
            af[f][2] = __float_as_uint(AsP[(kc * 8 + tig + 4) * 136 + mr]);    \
            af[f][3] = __float_as_uint(AsP[(kc * 8 + tig + 4) * 136 + mr + 8]);\
        }                                                                      \
        _Pragma("unroll")                                                      \
        for (int j = 0; j < 8; j++) {                                          \
            int nc = wn * 64 + j * 8 + gid;                                    \
            uint32_t b0 = __float_as_uint(BsP[(kc * 8 + tig) * 136 + nc]);     \
            uint32_t b1 = __float_as_uint(BsP[(kc * 8 + tig + 4) * 136 + nc]); \
            mma8(acc[0][j], af[0], b0, b1);                                    \
            mma8(acc[1][j], af[1], b0, b1);                                    \
        }                                                                      \
    }

#define GEMM_STAGE32(AsP, BsP)                                                 \
    _Pragma("unroll")                                                          \
    for (int kc = 0; kc < 4; kc++) {                                           \
        uint32_t af[2][4];                                                     \
        _Pragma("unroll")                                                      \
        for (int f = 0; f < 2; f++) {                                          \
            int mr = wm * 32 + f * 16 + gid;                                   \
            af[f][0] = __float_as_uint(AsP[(kc * 8 + tig) * 136 + mr]);        \
            af[f][1] = __float_as_uint(AsP[(kc * 8 + tig) * 136 + mr + 8]);    \
            af[f][2] = __float_as_uint(AsP[(kc * 8 + tig + 4) * 136 + mr]);    \
            af[f][3] = __float_as_uint(AsP[(kc * 8 + tig + 4) * 136 + mr + 8]);\
        }                                                                      \
        _Pragma("unroll")                                                      \
        for (int j = 0; j < 8; j++) {                                          \
            int nc = wn * 64 + j * 8 + gid;                                    \
            uint32_t b0 = __float_as_uint(BsP[(kc * 8 + tig) * 136 + nc]);     \
            uint32_t b1 = __float_as_uint(BsP[(kc * 8 + tig + 4) * 136 + nc]); \
            mma8(acc[0][j], af[0], b0, b1);                                    \
            mma8(acc[1][j], af[1], b0, b1);                                    \
        }                                                                      \
    }

// ---------------------------------------------------------------------------
// Fused Q/K/V projection: grid (32, 2, 6), z = mat*2 + b. 4-stage BK=16.
// ---------------------------------------------------------------------------
__global__ __launch_bounds__(256) void gemm_qkv(
    const float* __restrict__ wr,
    const float* __restrict__ bq, const float* __restrict__ bk,
    const float* __restrict__ bv,
    const float* __restrict__ x, const float* __restrict__ src,
    float* __restrict__ qo, float* __restrict__ ko, float* __restrict__ vo)
{
    extern __shared__ float dsm[];
    float* As = dsm;            // 4 stages x 2176
    float* Bs = dsm + 8704;     // 4 stages x 2176
    const int z = blockIdx.z, b = z & 1, mat = z >> 1;
    const float* W    = wr + mat * 65536;
    const float* bias = (mat == 0) ? bq : (mat == 1) ? bk : bv;
    const float* in   = (mat == 0) ? x : src;
    const int m0 = blockIdx.y * 128, n0 = blockIdx.x * 128;
    const int tid = threadIdx.x, wid = tid >> 5, lane = tid & 31;
    const int gid = lane >> 2, tig = lane & 3;
    const int wm = wid & 3, wn = wid >> 2;
    const uint32_t sA = smem_u32(As), sB = smem_u32(Bs);
    const int r0 = tid >> 5, c0 = (tid & 31) * 4;

    auto load_async = [&](int buf, int k0) {
        #pragma unroll
        for (int p = 0; p < 2; p++) {
            int r = r0 + p * 8;
            CP_ASYNC16(sA + (buf * 2176 + r * 136 + c0) * 4,
                       &W[(size_t)(k0 + r) * 256 + m0 + c0]);
            CP_ASYNC16(sB + (buf * 2176 + r * 136 + c0) * 4,
                       &in[((size_t)b * 256 + k0 + r) * NLEN + n0 + c0]);
        }
        CP_COMMIT();
    };

    load_async(0, 0);
    load_async(1, 16);
    load_async(2, 32);

    float acc[2][8][4] = {};
    for (int s = 0; s < 16; s++) {
        CP_WAIT2();
        __syncthreads();
        if (s + 3 < 16) load_async((s + 3) & 3, (s + 3) * 16);
        else            CP_COMMIT();   // empty group keeps wait_group math exact
        const float* AsP = As + (s & 3) * 2176;
        const float* BsP = Bs + (s & 3) * 2176;
        GEMM_STAGE16(AsP, BsP)
    }

    const float scl = (mat == 0) ? 0.125f : 1.0f;
    #pragma unroll
    for (int f = 0; f < 2; f++)
        #pragma unroll
        for (int j = 0; j < 8; j++) {
            int m_lo = m0 + wm * 32 + f * 16 + gid;
            int m_hi = m_lo + 8;
            int n = n0 + wn * 64 + j * 8 + 2 * tig;
            float blo = bias[m_lo], bhi = bias[m_hi];
            float v00 = acc[f][j][0] + blo, v01 = acc[f][j][1] + blo;
            float v10 = acc[f][j][2] + bhi, v11 = acc[f][j][3] + bhi;
            if (mat < 2) {
                float* out = (mat == 0) ? qo : ko;
                v00 *= scl; v01 *= scl; v10 *= scl; v11 *= scl;
                int dl = m_lo >> 2, hl = m_lo & 3;
                int dh2 = m_hi >> 2, hh2 = m_hi & 3;
                int dlp = (dl & ~7) | perm8(dl & 7);
                int dhp = (dh2 & ~7) | perm8(dh2 & 7);
                float* ol = out + (((size_t)b * NH + hl) * NLEN) * 64;
                float* oh = out + (((size_t)b * NH + hh2) * NLEN) * 64;
                ol[(size_t)(n)     * 64 + dlp] = f2tf32f(v00);
                ol[(size_t)(n + 1) * 64 + dlp] = f2tf32f(v01);
                oh[(size_t)(n)     * 64 + dhp] = f2tf32f(v10);
                oh[(size_t)(n + 1) * 64 + dhp] = f2tf32f(v11);
            } else {
                int na  = (n & ~7) | perm8(n & 7);
                int nb2 = ((n + 1) & ~7) | perm8((n + 1) & 7);
                float* ob = vo + (size_t)b * 256 * NLEN;
                ob[(size_t)m_lo * NLEN + na]  = f2tf32f(v00);
                ob[(size_t)m_lo * NLEN + nb2] = f2tf32f(v01);
                ob[(size_t)m_hi * NLEN + na]  = f2tf32f(v10);
                ob[(size_t)m_hi * NLEN + nb2] = f2tf32f(v11);
            }
        }
}

// ---------------------------------------------------------------------------
// 4-stage GEMM for msg (MODE 0: out rna-rounded) and cat (MODE 3: B=concat).
// ---------------------------------------------------------------------------
template <int MODE>
__global__ __launch_bounds__(256) void gemm_ms(
    const float* __restrict__ W, const float* __restrict__ bias,
    const float* __restrict__ in0, const float* __restrict__ in1,
    float* __restrict__ out)
{
    extern __shared__ float dsm[];
    float* As = dsm;
    float* Bs = dsm + 8704;
    const int K = (MODE == 3) ? 512 : 256;
    const int M = (MODE == 3) ? 512 : 256;
    const int S = K / 16;
    const int b = blockIdx.z;
    const int m0 = blockIdx.y * 128, n0 = blockIdx.x * 128;
    const int tid = threadIdx.x, wid = tid >> 5, lane = tid & 31;
    const int gid = lane >> 2, tig = lane & 3;
    const int wm = wid & 3, wn = wid >> 2;
    const uint32_t sA = smem_u32(As), sB = smem_u32(Bs);
    const int r0 = tid >> 5, c0 = (tid & 31) * 4;

    auto load_async = [&](int buf, int k0) {
        #pragma unroll
        for (int p = 0; p < 2; p++) {
            int r = r0 + p * 8;
            CP_ASYNC16(sA + (buf * 2176 + r * 136 + c0) * 4,
                       &W[(size_t)(k0 + r) * M + m0 + c0]);
            const float* src;
            if (MODE == 3)
                src = (k0 < 256)
                    ? in0 + ((size_t)b * 256 + k0 + r) * NLEN
                    : in1 + ((size_t)b * 256 + (k0 - 256) + r) * NLEN;
            else
                src = in0 + ((size_t)b * 256 + k0 + r) * NLEN;
            CP_ASYNC16(sB + (buf * 2176 + r * 136 + c0) * 4, src + n0 + c0);
        }
        CP_COMMIT();
    };

    load_async(0, 0);
    load_async(1, 16);
    load_async(2, 32);

    float acc[2][8][4] = {};
    for (int s = 0; s < S; s++) {
        CP_WAIT2();
        __syncthreads();
        if (s + 3 < S) load_async((s + 3) & 3, (s + 3) * 16);
        else           CP_COMMIT();
        const float* AsP = As + (s & 3) * 2176;
        const float* BsP = Bs + (s & 3) * 2176;
        GEMM_STAGE16(AsP, BsP)
    }

    #pragma unroll
    for (int f = 0; f < 2; f++)
        #pragma unroll
        for (int j = 0; j < 8; j++) {
            int m_lo = m0 + wm * 32 + f * 16 + gid;
            int m_hi = m_lo + 8;
            int n = n0 + wn * 64 + j * 8 + 2 * tig;
            float blo = bias[m_lo], bhi = bias[m_hi];
            float v00 = acc[f][j][0] + blo, v01 = acc[f][j][1] + blo;
            float v10 = acc[f][j][2] + bhi, v11 = acc[f][j][3] + bhi;
            if (MODE == 0) {
                v00 = f2tf32f(v00); v01 = f2tf32f(v01);
                v10 = f2tf32f(v10); v11 = f2tf32f(v11);
            }
            float* ob = out + (size_t)b * M * NLEN;
            *(float2*)&ob[(size_t)m_lo * NLEN + n] = make_float2(v00, v01);
            *(float2*)&ob[(size_t)m_hi * NLEN + n] = make_float2(v10, v11);
        }
}

// ---------------------------------------------------------------------------
// bn GEMM (R8-verified): out = W2 @ relu(h*scale+shift) + b2. BK=32 double
// buffer; B path is LDG -> BN transform -> STS.
// ---------------------------------------------------------------------------
__global__ __launch_bounds__(256) void gemm_bn(
    const float* __restrict__ W, const float* __restrict__ bias,
    const float* __restrict__ hbuf,
    const float* __restrict__ scale, const float* __restrict__ shift,
    float* __restrict__ out)
{
    extern __shared__ float dsm[];
    float* As = dsm;            // 2 x 4352
    float* Bs = dsm + 8704;     // 2 x 4352
    const int b = blockIdx.z;
    const int m0 = blockIdx.y * 128, n0 = blockIdx.x * 128;
    const int tid = threadIdx.x, wid = tid >> 5, lane = tid & 31;
    const int gid = lane >> 2, tig = lane & 3;
    const int wm = wid & 3, wn = wid >> 2;
    const uint32_t sA = smem_u32(As);
    const int r0 = tid >> 5, c0 = (tid & 31) * 4;

    float4 br[4];
    float  bsc[4], bsh[4];

    auto load_a = [&](int buf, int k0) {
        #pragma unroll
        for (int p = 0; p < 4; p++) {
            int r = r0 + p * 8;
            CP_ASYNC16(sA + (buf * 4352 + r * 136 + c0) * 4,
                       &W[(size_t)(k0 + r) * 256 + m0 + c0]);
        }
        CP_COMMIT();
    };
    auto load_b_regs = [&](int k0) {
        #pragma unroll
        for (int p = 0; p < 4; p++) {
            int r = r0 + p * 8;
            br[p] = *(const float4*)&hbuf[((size_t)b * 512 + k0 + r) * NLEN + n0 + c0];
            bsc[p] = scale[k0 + r];
            bsh[p] = shift[k0 + r];
        }
    };
    auto sts_b = [&](int buf) {
        #pragma unroll
        for (int p = 0; p < 4; p++) {
            int r = r0 + p * 8;
            float4 v = br[p];
            v.x = f2tf32f(fmaxf(fmaf(v.x, bsc[p], bsh[p]), 0.0f));
            v.y = f2tf32f(fmaxf(fmaf(v.y, bsc[p], bsh[p]), 0.0f));
            v.z = f2tf32f(fmaxf(fmaf(v.z, bsc[p], bsh[p]), 0.0f));
            v.w = f2tf32f(fmaxf(fmaf(v.w, bsc[p], bsh[p]), 0.0f));
            *(float4*)&Bs[buf * 4352 + r * 136 + c0] = v;
        }
    };

    load_b_regs(0);
    load_a(0, 0);
    CP_WAIT0();
    sts_b(0);
    __syncthreads();

    float acc[2][8][4] = {};
    for (int s = 0; s < 16; s++) {
        const int cur = s & 1, nxt = cur ^ 1;
        if (s + 1 < 16) {
            load_a(nxt, (s + 1) * 32);
            load_b_regs((s + 1) * 32);
        }
        const float* AsP = As + cur * 4352;
        const float* BsP = Bs + cur * 4352;
        GEMM_STAGE32(AsP, BsP)
        if (s + 1 < 16) sts_b(nxt);
        CP_WAIT0();
        __syncthreads();
    }

    #pragma unroll
    for (int f = 0; f < 2; f++)
        #pragma unroll
        for (int j = 0; j < 8; j++) {
            int m_lo = m0 + wm * 32 + f * 16 + gid;
            int m_hi = m_lo + 8;
            int n = n0 + wn * 64 + j * 8 + 2 * tig;
            float blo = bias[m_lo], bhi = bias[m_hi];
            float* ob = out + (size_t)b * 256 * NLEN;
            *(float2*)&ob[(size_t)m_lo * NLEN + n] =
                make_float2(acc[f][j][0] + blo, acc[f][j][1] + blo);
            *(float2*)&ob[(size_t)m_hi * NLEN + n] =
                make_float2(acc[f][j][2] + bhi, acc[f][j][3] + bhi);
        }
}

// ---------------------------------------------------------------------------
// BatchNorm (train-mode) batch statistics -> per-channel (scale, shift)
// ---------------------------------------------------------------------------
__global__ __launch_bounds__(256) void bn_stats(
    const float* __restrict__ hbuf,
    const float* __restrict__ gamma, const float* __restrict__ beta,
    float* __restrict__ scale, float* __restrict__ shift)
{
    const int c = blockIdx.x;
    float s = 0.f, ss = 0.f;
    for (int idx = threadIdx.x; idx < NB * NLEN; idx += 256) {
        int b = idx >> 12, n = idx & (NLEN - 1);
        float v = hbuf[((size_t)b * 512 + c) * NLEN + n];
        s += v;
        ss = fmaf(v, v, ss);
    }
    #pragma unroll
    for (int off = 16; off; off >>= 1) {
        s  += __shfl_xor_sync(0xffffffffu, s, off);
        ss += __shfl_xor_sync(0xffffffffu, ss, off);
    }
    __shared__ float rs[8], rss[8];
    int w = threadIdx.x >> 5;
    if ((threadIdx.x & 31) == 0) { rs[w] = s; rss[w] = ss; }
    __syncthreads();
    if (threadIdx.x == 0) {
        float S = 0.f, SS = 0.f;
        #pragma unroll
        for (int i = 0; i < 8; i++) { S += rs[i]; SS += rss[i]; }
        float mean = S * (1.0f / (NB * NLEN));
        float var  = SS * (1.0f / (NB * NLEN)) - mean * mean;
        float rstd = rsqrtf(var + 1e-5f);
        float a = gamma[c] * rstd;
        scale[c] = a;
        shift[c] = beta[c] - mean * a;
    }
}

// ===========================================================================
// tf32 mma.sync flash attention, pitch-72 SMEM (conflict-free float2 LDS).
// ===========================================================================
#define KP 72
#define KS_F 0
#define VS_F 9216
#define PS_F 18432
#define FLASH_SMEM ((18432 + 9216) * 4)   // 110592 B -> 2 CTAs/SM

__global__ __launch_bounds__(256, 2) void flash_mma(
    const float* __restrict__ q2, const float* __restrict__ k2,
    const float* __restrict__ v, float* __restrict__ attn)
{
    extern __shared__ float sm[];
    const uint32_t smb = smem_u32(sm);
    const int tid = threadIdx.x;
    const int wid = tid >> 5, lane = tid & 31;
    const int gid = lane >> 2, tig = lane & 3;
    const int b = blockIdx.z, hh = blockIdx.y;
    const int q0 = blockIdx.x * 128;
    const size_t bh = (size_t)b * NH + hh;
    const float* kbase = k2 + bh * NLEN * 64;
    const float* vbase = v + ((size_t)b * DIM + hh) * NLEN;

    // ---- stage Q (already scaled + tf32); pitch 72
    #pragma unroll
    for (int i = 0; i < 8; i++) {
        int idx = tid + i * 256;
        int r = idx >> 4, c = (idx & 15) * 4;
        *(float4*)&sm[PS_F + r * KP + c] =
            *(const float4*)&q2[(bh * NLEN + q0 + r) * 64 + c];
    }
    __syncthreads();

    const int row0 = wid * 16 + gid, row1 = row0 + 8;
    uint32_t aq[8][4];
    #pragma unroll
    for (int k = 0; k < 8; k++) {
        float2 fa = *(const float2*)&sm[PS_F + row0 * KP + k * 8 + 2 * tig];
        float2 fb = *(const float2*)&sm[PS_F + row1 * KP + k * 8 + 2 * tig];
        aq[k][0] = __float_as_uint(fa.x);
        aq[k][1] = __float_as_uint(fb.x);
        aq[k][2] = __float_as_uint(fa.y);
        aq[k][3] = __float_as_uint(fb.y);
    }
    __syncthreads();

    // ---- prologue: tile 0 -> buffer 0
    {
        #pragma unroll
        for (int i = 0; i < 4; i++) {
            int idx = tid + i * 256;
            int r = idx >> 4, c = (idx & 15) * 4;
            CP_ASYNC16(smb + (KS_F + r * KP + c) * 4, kbase + (size_t)r * 64 + c);
            CP_ASYNC16(smb + (VS_F + r * KP + c) * 4,
                       vbase + (size_t)r * NH * NLEN + c);
        }
        CP_COMMIT();
        CP_WAIT0();
        __syncthreads();
    }

    float o[8][4] = {};
    float l0 = 0.f, l1 = 0.f;
    float* Pw = sm + PS_F + wid * 16 * KP;

    for (int t = 0; t < NLEN / 64; t++) {
        const int bufc = t & 1;
        if (t + 1 < NLEN / 64) {
            const int bn = (t + 1) & 1;
            const int m0 = (t + 1) * 64;
            #pragma unroll
            for (int i = 0; i < 4; i++) {
                int idx = tid + i * 256;
                int r = idx >> 4, c = (idx & 15) * 4;
                CP_ASYNC16(smb + (KS_F + bn * 4608 + r * KP + c) * 4,
                           kbase + (size_t)(m0 + r) * 64 + c);
                CP_ASYNC16(smb + (VS_F + bn * 4608 + r * KP + c) * 4,
                           vbase + (size_t)r * NH * NLEN + m0 + c);
            }
            CP_COMMIT();
        }

        // ---- S = Q @ K^T
        const float* Ks = sm + KS_F + bufc * 4608;
        float s[8][4] = {};
        #pragma unroll
        for (int k = 0; k < 8; k++) {
            #pragma unroll
            for (int j = 0; j < 8; j++) {
                float2 kb = *(const float2*)&Ks[(j * 8 + gid) * KP + k * 8 + 2 * tig];
                mma8(s[j], aq[k], __float_as_uint(kb.x), __float_as_uint(kb.y));
            }
        }

        // ---- softmax; lsum over ROUNDED p
        #pragma unroll
        for (int j = 0; j < 8; j++) {
            float p0 = f2tf32f(__expf(s[j][0]));
            float p1 = f2tf32f(__expf(s[j][1]));
            float p2 = f2tf32f(__expf(s[j][2]));
            float p3 = f2tf32f(__expf(s[j][3]));
            l0 += p0 + p1;
            l1 += p2 + p3;
            *(float2*)&Pw[gid * KP + j * 8 + 2 * tig] = make_float2(p0, p1);
            *(float2*)&Pw[(gid + 8) * KP + j * 8 + 2 * tig] = make_float2(p2, p3);
        }
        __syncwarp();

        // ---- O += P @ V
        const float* Vs = sm + VS_F + bufc * 4608;
        #pragma unroll
        for (int k = 0; k < 8; k++) {
            uint32_t ap[4];
            ap[0] = __float_as_uint(Pw[gid * KP + k * 8 + tig]);
            ap[1] = __float_as_uint(Pw[(gid + 8) * KP + k * 8 + tig]);
            ap[2] = __float_as_uint(Pw[gid * KP + k * 8 + tig + 4]);
            ap[3] = __float_as_uint(Pw[(gid + 8) * KP + k * 8 + tig + 4]);
            #pragma unroll
            for (int j = 0; j < 8; j++) {
                float2 vb = *(const float2*)&Vs[(j * 8 + gid) * KP + k * 8 + 2 * tig];
                mma8(o[j], ap, __float_as_uint(vb.x), __float_as_uint(vb.y));
            }
        }
        __syncwarp();

        CP_WAIT0();
        __syncthreads();
    }

    // ---- finalize
    l0 += __shfl_xor_sync(0xffffffffu, l0, 1);
    l0 += __shfl_xor_sync(0xffffffffu, l0, 2);
    l1 += __shfl_xor_sync(0xffffffffu, l1, 1);
    l1 += __shfl_xor_sync(0xffffffffu, l1, 2);
    const float inv0 = 1.0f / l0, inv1 = 1.0f / l1;
    #pragma unroll
    for (int j = 0; j < 8; j++) {
        o[j][0] *= inv0; o[j][1] *= inv0;
        o[j][2] *= inv1; o[j][3] *= inv1;
    }

    // ---- stage O as [64 d][128 q] (pitch 132), rna-round, coalesced store
    __syncthreads();
    float* stage = sm;
    #pragma unroll
    for (int j = 0; j < 8; j++) {
        int d0 = j * 8 + 2 * tig;
        stage[(d0 + 0) * 132 + row0] = o[j][0];
        stage[(d0 + 1) * 132 + row0] = o[j][1];
        stage[(d0 + 0) * 132 + row1] = o[j][2];
        stage[(d0 + 1) * 132 + row1] = o[j][3];
    }
    __syncthreads();
    #pragma unroll
    for (int i = 0; i < 8; i++) {
        int idx = tid + i * 256;
        int r = idx >> 5, c = (idx & 31) * 4;
        float4 t = *(const float4*)&stage[r * 132 + c];
        t.x = f2tf32f(t.x); t.y = f2tf32f(t.y);
        t.z = f2tf32f(t.z); t.w = f2tf32f(t.w);
        *(float4*)&attn[((size_t)b * DIM + r * NH + hh) * NLEN + q0 + c] = t;
    }
}

// ---------------------------------------------------------------------------
static float* symaddr(const void* sym) {
    void* p = nullptr;
    cudaGetSymbolAddress(&p, sym);
    return (float*)p;
}

extern "C" void kernel_launch(void* const* d_in, const int* in_sizes, int n_in,
                              void* d_out, int out_size)
{
    const float* x      = (const float*)d_in[0];
    const float* source = (const float*)d_in[1];
    const float* Wq = (const float*)d_in[2];
    const float* bq = (const float*)d_in[3];
    const float* Wk = (const float*)d_in[4];
    const float* bk = (const float*)d_in[5];
    const float* Wv = (const float*)d_in[6];
    const float* bv = (const float*)d_in[7];
    const float* Wo = (const float*)d_in[8];
    const float* bo = (const float*)d_in[9];
    const float* W1 = (const float*)d_in[10];
    const float* b1 = (const float*)d_in[11];
    const float* gamma = (const float*)d_in[12];
    const float* beta  = (const float*)d_in[13];
    const float* W2 = (const float*)d_in[14];
    const float* b2 = (const float*)d_in[15];
    float* out = (float*)d_out;

    float* q    = symaddr(g_q);
    float* kbuf = symaddr(g_k);
    float* vbuf = symaddr(g_v);
    float* attn = symaddr(g_attn);
    float* msg  = symaddr(g_msg);
    float* hbuf = symaddr(g_h);
    float* scl  = symaddr(g_scale);
    float* shf  = symaddr(g_shift);
    float* wr   = symaddr(g_wr);

    cudaFuncSetAttribute(flash_mma,
                         cudaFuncAttributeMaxDynamicSharedMemorySize, FLASH_SMEM);
    cudaFuncSetAttribute(gemm_qkv,
                         cudaFuncAttributeMaxDynamicSharedMemorySize, GEMM_SMEM);
    cudaFuncSetAttribute(gemm_ms<0>,
                         cudaFuncAttributeMaxDynamicSharedMemorySize, GEMM_SMEM);
    cudaFuncSetAttribute(gemm_ms<3>,
                         cudaFuncAttributeMaxDynamicSharedMemorySize, GEMM_SMEM);
    cudaFuncSetAttribute(gemm_bn,
                         cudaFuncAttributeMaxDynamicSharedMemorySize, GEMM_SMEM);

    dim3 blk(256);
    // weights -> tf32 (rna)
    round_weights<<<2560, blk>>>(Wq, Wk, Wv, Wo, W1, W2, wr);
    // fused Q/K/V projections
    gemm_qkv<<<dim3(32, 2, 6), blk, GEMM_SMEM>>>(
        wr, bq, bk, bv, x, source, q, kbuf, vbuf);
    // attention
    flash_mma<<<dim3(32, NH, NB), blk, FLASH_SMEM>>>(q, kbuf, vbuf, attn);
    // output projection (rounds output)
    gemm_ms<0><<<dim3(32, 2, 2), blk, GEMM_SMEM>>>(
        wr + WR_O, bo, attn, nullptr, msg);
    // MLP layer 1 over concat([x, msg])
    gemm_ms<3><<<dim3(32, 4, 2), blk, GEMM_SMEM>>>(
        wr + WR_1, b1, x, msg, hbuf);
    // batchnorm stats -> per-channel scale/shift
    bn_stats<<<512, blk>>>(hbuf, gamma, beta, scl, shf);
    // MLP layer 2 with fused normalize+relu (final output)
    gemm_bn<<<dim3(32, 2, 2), blk, GEMM_SMEM>>>(
        wr + WR_2, b2, hbuf, scl, shf, out);
}

// round 14
// speedup vs baseline: 1.1407x; 1.0932x over previous
#include <cuda_runtime.h>
#include <math.h>
#include <stdint.h>

#define NB    2
#define DIM   256
#define NLEN  4096
#define NH    4

// ---------------- scratch (allocation-free: device globals) ----------------
__device__ float g_q[NB * DIM * NLEN];    // [b][h][n][d-paired] tf32, pre-scaled
__device__ float g_k[NB * DIM * NLEN];    // [b][h][m][d-paired] tf32
__device__ float g_v[NB * DIM * NLEN];    // [b][c][m-paired] tf32 (c = dh*NH+h)
__device__ float g_attn[NB * DIM * NLEN]; // [b][c][n] tf32-rounded
__device__ float g_msg[NB * DIM * NLEN];  // tf32-rounded
__device__ float g_h[NB * 2 * DIM * NLEN];
__device__ float g_scale[2 * DIM];
__device__ float g_shift[2 * DIM];
__device__ float g_wr[655360];            // rna-rounded weights
#define WR_Q  0
#define WR_K  65536
#define WR_V  131072
#define WR_O  196608
#define WR_1  262144
#define WR_2  524288

// ======================= helpers ======================
__device__ __forceinline__ uint32_t smem_u32(const void* p) {
    uint32_t a;
    asm("{ .reg .u64 t; cvta.to.shared.u64 t, %1; cvt.u32.u64 %0, t; }"
        : "=r"(a) : "l"(p));
    return a;
}

#define CP_ASYNC16(smaddr, gptr) \
    asm volatile("cp.async.ca.shared.global [%0], [%1], 16;" \
                 :: "r"(smaddr), "l"(gptr) : "memory")
#define CP_COMMIT() asm volatile("cp.async.commit_group;" ::: "memory")
#define CP_WAIT0()  asm volatile("cp.async.wait_group 0;" ::: "memory")
#define CP_WAIT2()  asm volatile("cp.async.wait_group 2;" ::: "memory")

__device__ __forceinline__ float f2tf32f(float x) {
    uint32_t u;
    asm("cvt.rna.tf32.f32 %0, %1;" : "=r"(u) : "f"(x));
    return __uint_as_float(u);
}
__device__ __forceinline__ int perm8(int p) { return (p < 4) ? 2 * p : 2 * (p - 4) + 1; }

// D += A @ B : m16n8k8 tf32; A row-major, B col-major, C fp32
__device__ __forceinline__ void mma8(float* c, const uint32_t* a,
                                     uint32_t b0, uint32_t b1) {
    asm volatile(
        "mma.sync.aligned.m16n8k8.row.col.f32.tf32.tf32.f32 "
        "{%0,%1,%2,%3}, {%4,%5,%6,%7}, {%8,%9}, {%0,%1,%2,%3};"
        : "+f"(c[0]), "+f"(c[1]), "+f"(c[2]), "+f"(c[3])
        : "r"(a[0]), "r"(a[1]), "r"(a[2]), "r"(a[3]), "r"(b0), "r"(b1));
}

// ---------------------------------------------------------------------------
// One-shot weight rounding to tf32 (rna)
// ---------------------------------------------------------------------------
__global__ __launch_bounds__(256) void round_weights(
    const float* __restrict__ wq, const float* __restrict__ wk,
    const float* __restrict__ wv, const float* __restrict__ wo,
    const float* __restrict__ w1, const float* __restrict__ w2,
    float* __restrict__ dst)
{
    int i = blockIdx.x * 256 + threadIdx.x;
    if      (i < 65536)  dst[i] = f2tf32f(wq[i]);
    else if (i < 131072) dst[i] = f2tf32f(wk[i - 65536]);
    else if (i < 196608) dst[i] = f2tf32f(wv[i - 131072]);
    else if (i < 262144) dst[i] = f2tf32f(wo[i - 196608]);
    else if (i < 524288) dst[i] = f2tf32f(w1[i - 262144]);
    else if (i < 655360) dst[i] = f2tf32f(w2[i - 524288]);
}

// ===========================================================================
// GEMM machinery. 128x128 CTA tile, 8 warps (4m x 2n), warp tile 32m x 64n.
// 4-stage cp.async pipeline at BK=16 (qkv/msg/cat). SMEM = 8 x 2176 floats.
// ===========================================================================
#define GEMM_SMEM (17408 * 4)

#define GEMM_STAGE16(AsP, BsP)                                                 \
    _Pragma("unroll")                                                          \
    for (int kc = 0; kc < 2; kc++) {                                           \
        uint32_t af[2][4];                                                     \
        _Pragma("unroll")                                                      \
        for (int f = 0; f < 2; f++) {                                          \
            int mr = wm * 32 + f * 16 + gid;                                   \
            af[f][0] = __float_as_uint(AsP[(kc * 8 + tig) * 136 + mr]);        \
            af[f][1] = __float_as_uint(AsP[(kc * 8 + tig) * 136 + mr + 8]);    \
            af[f][2] = __float_as_uint(AsP[(kc * 8 + tig + 4) * 136 + mr]);    \
            af[f][3] = __float_as_uint(AsP[(kc * 8 + tig + 4) * 136 + mr + 8]);\
        }                                                                      \
        _Pragma("unroll")                                                      \
        for (int j = 0; j < 8; j++) {                                          \
            int nc = wn * 64 + j * 8 + gid;                                    \
            uint32_t b0 = __float_as_uint(BsP[(kc * 8 + tig) * 136 + nc]);     \
            uint32_t b1 = __float_as_uint(BsP[(kc * 8 + tig + 4) * 136 + nc]); \
            mma8(acc[0][j], af[0], b0, b1);                                    \
            mma8(acc[1][j], af[1], b0, b1);                                    \
        }                                                                      \
    }

// ---------------------------------------------------------------------------
// Fused Q/K/V projection: grid (32, 2, 6), z = mat*2 + b. 4-stage BK=16.
// ---------------------------------------------------------------------------
__global__ __launch_bounds__(256) void gemm_qkv(
    const float* __restrict__ wr,
    const float* __restrict__ bq, const float* __restrict__ bk,
    const float* __restrict__ bv,
    const float* __restrict__ x, const float* __restrict__ src,
    float* __restrict__ qo, float* __restrict__ ko, float* __restrict__ vo)
{
    extern __shared__ float dsm[];
    float* As = dsm;            // 4 stages x 2176
    float* Bs = dsm + 8704;     // 4 stages x 2176
    const int z = blockIdx.z, b = z & 1, mat = z >> 1;
    const float* W    = wr + mat * 65536;
    const float* bias = (mat == 0) ? bq : (mat == 1) ? bk : bv;
    const float* in   = (mat == 0) ? x : src;
    const int m0 = blockIdx.y * 128, n0 = blockIdx.x * 128;
    const int tid = threadIdx.x, wid = tid >> 5, lane = tid & 31;
    const int gid = lane >> 2, tig = lane & 3;
    const int wm = wid & 3, wn = wid >> 2;
    const uint32_t sA = smem_u32(As), sB = smem_u32(Bs);
    const int r0 = tid >> 5, c0 = (tid & 31) * 4;

    auto load_async = [&](int buf, int k0) {
        #pragma unroll
        for (int p = 0; p < 2; p++) {
            int r = r0 + p * 8;
            CP_ASYNC16(sA + (buf * 2176 + r * 136 + c0) * 4,
                       &W[(size_t)(k0 + r) * 256 + m0 + c0]);
            CP_ASYNC16(sB + (buf * 2176 + r * 136 + c0) * 4,
                       &in[((size_t)b * 256 + k0 + r) * NLEN + n0 + c0]);
        }
        CP_COMMIT();
    };

    load_async(0, 0);
    load_async(1, 16);
    load_async(2, 32);

    float acc[2][8][4] = {};
    for (int s = 0; s < 16; s++) {
        CP_WAIT2();
        __syncthreads();
        if (s + 3 < 16) load_async((s + 3) & 3, (s + 3) * 16);
        else            CP_COMMIT();
        const float* AsP = As + (s & 3) * 2176;
        const float* BsP = Bs + (s & 3) * 2176;
        GEMM_STAGE16(AsP, BsP)
    }

    const float scl = (mat == 0) ? 0.125f : 1.0f;
    #pragma unroll
    for (int f = 0; f < 2; f++)
        #pragma unroll
        for (int j = 0; j < 8; j++) {
            int m_lo = m0 + wm * 32 + f * 16 + gid;
            int m_hi = m_lo + 8;
            int n = n0 + wn * 64 + j * 8 + 2 * tig;
            float blo = bias[m_lo], bhi = bias[m_hi];
            float v00 = acc[f][j][0] + blo, v01 = acc[f][j][1] + blo;
            float v10 = acc[f][j][2] + bhi, v11 = acc[f][j][3] + bhi;
            if (mat < 2) {
                float* out = (mat == 0) ? qo : ko;
                v00 *= scl; v01 *= scl; v10 *= scl; v11 *= scl;
                int dl = m_lo >> 2, hl = m_lo & 3;
                int dh2 = m_hi >> 2, hh2 = m_hi & 3;
                int dlp = (dl & ~7) | perm8(dl & 7);
                int dhp = (dh2 & ~7) | perm8(dh2 & 7);
                float* ol = out + (((size_t)b * NH + hl) * NLEN) * 64;
                float* oh = out + (((size_t)b * NH + hh2) * NLEN) * 64;
                ol[(size_t)(n)     * 64 + dlp] = f2tf32f(v00);
                ol[(size_t)(n + 1) * 64 + dlp] = f2tf32f(v01);
                oh[(size_t)(n)     * 64 + dhp] = f2tf32f(v10);
                oh[(size_t)(n + 1) * 64 + dhp] = f2tf32f(v11);
            } else {
                int na  = (n & ~7) | perm8(n & 7);
                int nb2 = ((n + 1) & ~7) | perm8((n + 1) & 7);
                float* ob = vo + (size_t)b * 256 * NLEN;
                ob[(size_t)m_lo * NLEN + na]  = f2tf32f(v00);
                ob[(size_t)m_lo * NLEN + nb2] = f2tf32f(v01);
                ob[(size_t)m_hi * NLEN + na]  = f2tf32f(v10);
                ob[(size_t)m_hi * NLEN + nb2] = f2tf32f(v11);
            }
        }
}

// ---------------------------------------------------------------------------
// 4-stage GEMM for msg (MODE 0: out rna-rounded) and cat (MODE 3: B=concat).
// ---------------------------------------------------------------------------
template <int MODE>
__global__ __launch_bounds__(256) void gemm_ms(
    const float* __restrict__ W, const float* __restrict__ bias,
    const float* __restrict__ in0, const float* __restrict__ in1,
    float* __restrict__ out)
{
    extern __shared__ float dsm[];
    float* As = dsm;
    float* Bs = dsm + 8704;
    const int K = (MODE == 3) ? 512 : 256;
    const int M = (MODE == 3) ? 512 : 256;
    const int S = K / 16;
    const int b = blockIdx.z;
    const int m0 = blockIdx.y * 128, n0 = blockIdx.x * 128;
    const int tid = threadIdx.x, wid = tid >> 5, lane = tid & 31;
    const int gid = lane >> 2, tig = lane & 3;
    const int wm = wid & 3, wn = wid >> 2;
    const uint32_t sA = smem_u32(As), sB = smem_u32(Bs);
    const int r0 = tid >> 5, c0 = (tid & 31) * 4;

    auto load_async = [&](int buf, int k0) {
        #pragma unroll
        for (int p = 0; p < 2; p++) {
            int r = r0 + p * 8;
            CP_ASYNC16(sA + (buf * 2176 + r * 136 + c0) * 4,
                       &W[(size_t)(k0 + r) * M + m0 + c0]);
            const float* src;
            if (MODE == 3)
                src = (k0 < 256)
                    ? in0 + ((size_t)b * 256 + k0 + r) * NLEN
                    : in1 + ((size_t)b * 256 + (k0 - 256) + r) * NLEN;
            else
                src = in0 + ((size_t)b * 256 + k0 + r) * NLEN;
            CP_ASYNC16(sB + (buf * 2176 + r * 136 + c0) * 4, src + n0 + c0);
        }
        CP_COMMIT();
    };

    load_async(0, 0);
    load_async(1, 16);
    load_async(2, 32);

    float acc[2][8][4] = {};
    for (int s = 0; s < S; s++) {
        CP_WAIT2();
        __syncthreads();
        if (s + 3 < S) load_async((s + 3) & 3, (s + 3) * 16);
        else           CP_COMMIT();
        const float* AsP = As + (s & 3) * 2176;
        const float* BsP = Bs + (s & 3) * 2176;
        GEMM_STAGE16(AsP, BsP)
    }

    #pragma unroll
    for (int f = 0; f < 2; f++)
        #pragma unroll
        for (int j = 0; j < 8; j++) {
            int m_lo = m0 + wm * 32 + f * 16 + gid;
            int m_hi = m_lo + 8;
            int n = n0 + wn * 64 + j * 8 + 2 * tig;
            float blo = bias[m_lo], bhi = bias[m_hi];
            float v00 = acc[f][j][0] + blo, v01 = acc[f][j][1] + blo;
            float v10 = acc[f][j][2] + bhi, v11 = acc[f][j][3] + bhi;
            if (MODE == 0) {
                v00 = f2tf32f(v00); v01 = f2tf32f(v01);
                v10 = f2tf32f(v10); v11 = f2tf32f(v11);
            }
            float* ob = out + (size_t)b * M * NLEN;
            *(float2*)&ob[(size_t)m_lo * NLEN + n] = make_float2(v00, v01);
            *(float2*)&ob[(size_t)m_hi * NLEN + n] = make_float2(v10, v11);
        }
}

// ---------------------------------------------------------------------------
// bn GEMM, 64-wide N tiles (verified correct in the R10 run):
// out = W2 @ relu(h*scale+shift) + b2. K=512, M=256. grid (128, 2).
// 8 warps (4m x 2n), warp tile 32m x 32n. smem 53248 B.
// ---------------------------------------------------------------------------
#define BN64_SMEM (13312 * 4)
__global__ __launch_bounds__(256) void gemm_bn64(
    const float* __restrict__ W, const float* __restrict__ bias,
    const float* __restrict__ hbuf,
    const float* __restrict__ scale, const float* __restrict__ shift,
    float* __restrict__ out)
{
    extern __shared__ float dsm[];
    float* As = dsm;
    float* Bs = dsm + 8704;
    const int ng = blockIdx.x * 64;
    const int b = ng >> 12, n0 = ng & (NLEN - 1);
    const int m0 = blockIdx.y * 128;
    const int tid = threadIdx.x, wid = tid >> 5, lane = tid & 31;
    const int gid = lane >> 2, tig = lane & 3;
    const int wm = wid & 3, wn = wid >> 2;
    const uint32_t sA = smem_u32(As);
    const int r0 = tid >> 5, c0 = (tid & 31) * 4;       // A loader
    const int r0b = tid >> 4, c0b = (tid & 15) * 4;     // B loader (64-wide)

    float4 br[2];
    float  bsc[2], bsh[2];

    auto load_a = [&](int buf, int k0) {
        #pragma unroll
        for (int p = 0; p < 4; p++) {
            int r = r0 + p * 8;
            CP_ASYNC16(sA + (buf * 4352 + r * 136 + c0) * 4,
                       &W[(size_t)(k0 + r) * 256 + m0 + c0]);
        }
        CP_COMMIT();
    };
    auto load_b_regs = [&](int k0) {
        #pragma unroll
        for (int p = 0; p < 2; p++) {
            int r = r0b + p * 16;
            br[p] = *(const float4*)&hbuf[((size_t)b * 512 + k0 + r) * NLEN + n0 + c0b];
            bsc[p] = scale[k0 + r];
            bsh[p] = shift[k0 + r];
        }
    };
    auto sts_b = [&](int buf) {
        #pragma unroll
        for (int p = 0; p < 2; p++) {
            int r = r0b + p * 16;
            float4 v = br[p];
            v.x = f2tf32f(fmaxf(fmaf(v.x, bsc[p], bsh[p]), 0.0f));
            v.y = f2tf32f(fmaxf(fmaf(v.y, bsc[p], bsh[p]), 0.0f));
            v.z = f2tf32f(fmaxf(fmaf(v.z, bsc[p], bsh[p]), 0.0f));
            v.w = f2tf32f(fmaxf(fmaf(v.w, bsc[p], bsh[p]), 0.0f));
            *(float4*)&Bs[buf * 2304 + r * 72 + c0b] = v;
        }
    };

    load_b_regs(0);
    load_a(0, 0);
    CP_WAIT0();
    sts_b(0);
    __syncthreads();

    float acc[2][4][4] = {};
    for (int s = 0; s < 16; s++) {
        const int cur = s & 1, nxt = cur ^ 1;
        if (s + 1 < 16) {
            load_a(nxt, (s + 1) * 32);
            load_b_regs((s + 1) * 32);
        }
        const float* AsP = As + cur * 4352;
        const float* BsP = Bs + cur * 2304;
        #pragma unroll
        for (int kc = 0; kc < 4; kc++) {
            uint32_t af[2][4];
            #pragma unroll
            for (int f = 0; f < 2; f++) {
                int mr = wm * 32 + f * 16 + gid;
                af[f][0] = __float_as_uint(AsP[(kc * 8 + tig) * 136 + mr]);
                af[f][1] = __float_as_uint(AsP[(kc * 8 + tig) * 136 + mr + 8]);
                af[f][2] = __float_as_uint(AsP[(kc * 8 + tig + 4) * 136 + mr]);
                af[f][3] = __float_as_uint(AsP[(kc * 8 + tig + 4) * 136 + mr + 8]);
            }
            #pragma unroll
            for (int j = 0; j < 4; j++) {
                int nc = wn * 32 + j * 8 + gid;
                uint32_t b0 = __float_as_uint(BsP[(kc * 8 + tig) * 72 + nc]);
                uint32_t b1 = __float_as_uint(BsP[(kc * 8 + tig + 4) * 72 + nc]);
                mma8(acc[0][j], af[0], b0, b1);
                mma8(acc[1][j], af[1], b0, b1);
            }
        }
        if (s + 1 < 16) sts_b(nxt);
        CP_WAIT0();
        __syncthreads();
    }

    #pragma unroll
    for (int f = 0; f < 2; f++)
        #pragma unroll
        for (int j = 0; j < 4; j++) {
            int m_lo = m0 + wm * 32 + f * 16 + gid;
            int m_hi = m_lo + 8;
            int n = n0 + wn * 32 + j * 8 + 2 * tig;
            float blo = bias[m_lo], bhi = bias[m_hi];
            float* ob = out + (size_t)b * 256 * NLEN;
            *(float2*)&ob[(size_t)m_lo * NLEN + n] =
                make_float2(acc[f][j][0] + blo, acc[f][j][1] + blo);
            *(float2*)&ob[(size_t)m_hi * NLEN + n] =
                make_float2(acc[f][j][2] + bhi, acc[f][j][3] + bhi);
        }
}

// ---------------------------------------------------------------------------
// BatchNorm (train-mode) batch statistics -> per-channel (scale, shift)
// ---------------------------------------------------------------------------
__global__ __launch_bounds__(256) void bn_stats(
    const float* __restrict__ hbuf,
    const float* __restrict__ gamma, const float* __restrict__ beta,
    float* __restrict__ scale, float* __restrict__ shift)
{
    const int c = blockIdx.x;
    float s = 0.f, ss = 0.f;
    for (int idx = threadIdx.x; idx < NB * NLEN; idx += 256) {
        int b = idx >> 12, n = idx & (NLEN - 1);
        float v = hbuf[((size_t)b * 512 + c) * NLEN + n];
        s += v;
        ss = fmaf(v, v, ss);
    }
    #pragma unroll
    for (int off = 16; off; off >>= 1) {
        s  += __shfl_xor_sync(0xffffffffu, s, off);
        ss += __shfl_xor_sync(0xffffffffu, ss, off);
    }
    __shared__ float rs[8], rss[8];
    int w = threadIdx.x >> 5;
    if ((threadIdx.x & 31) == 0) { rs[w] = s; rss[w] = ss; }
    __syncthreads();
    if (threadIdx.x == 0) {
        float S = 0.f, SS = 0.f;
        #pragma unroll
        for (int i = 0; i < 8; i++) { S += rs[i]; SS += rss[i]; }
        float mean = S * (1.0f / (NB * NLEN));
        float var  = SS * (1.0f / (NB * NLEN)) - mean * mean;
        float rstd = rsqrtf(var + 1e-5f);
        float a = gamma[c] * rstd;
        scale[c] = a;
        shift[c] = beta[c] - mean * a;
    }
}

// ===========================================================================
// tf32 mma.sync flash attention v2: 128 threads, 4 warps x 32 query rows.
// Each K/V B-fragment load now feeds TWO mmas (two m16 A-frags per warp),
// cutting shared-memory wavefronts per query by ~40% (the measured
// bottleneck). SMEM layout and addressing identical to the verified v1.
// ===========================================================================
#define KP 72
#define KS_F 0
#define VS_F 9216
#define PS_F 18432
#define FLASH_SMEM ((18432 + 9216) * 4)   // 110592 B -> 2 CTAs/SM

__global__ __launch_bounds__(128, 2) void flash_mma(
    const float* __restrict__ q2, const float* __restrict__ k2,
    const float* __restrict__ v, float* __restrict__ attn)
{
    extern __shared__ float sm[];
    const uint32_t smb = smem_u32(sm);
    const int tid = threadIdx.x;
    const int wid = tid >> 5, lane = tid & 31;
    const int gid = lane >> 2, tig = lane & 3;
    const int b = blockIdx.z, hh = blockIdx.y;
    const int q0 = blockIdx.x * 128;
    const size_t bh = (size_t)b * NH + hh;
    const float* kbase = k2 + bh * NLEN * 64;
    const float* vbase = v + ((size_t)b * DIM + hh) * NLEN;

    // ---- stage Q (already scaled + tf32, paired-d); pitch 72
    #pragma unroll
    for (int i = 0; i < 16; i++) {
        int idx = tid + i * 128;
        int r = idx >> 4, c = (idx & 15) * 4;
        *(float4*)&sm[PS_F + r * KP + c] =
            *(const float4*)&q2[(bh * NLEN + q0 + r) * 64 + c];
    }
    __syncthreads();

    // Q fragments: 2 m-frags per warp (rows wid*32 + f*16 + gid, +8)
    uint32_t aq[2][8][4];
    #pragma unroll
    for (int f = 0; f < 2; f++) {
        int ra = wid * 32 + f * 16 + gid, rb = ra + 8;
        #pragma unroll
        for (int k = 0; k < 8; k++) {
            float2 fa = *(const float2*)&sm[PS_F + ra * KP + k * 8 + 2 * tig];
            float2 fb = *(const float2*)&sm[PS_F + rb * KP + k * 8 + 2 * tig];
            aq[f][k][0] = __float_as_uint(fa.x);
            aq[f][k][1] = __float_as_uint(fb.x);
            aq[f][k][2] = __float_as_uint(fa.y);
            aq[f][k][3] = __float_as_uint(fb.y);
        }
    }
    __syncthreads();

    // ---- prologue: tile 0 -> buffer 0
    {
        #pragma unroll
        for (int i = 0; i < 8; i++) {
            int idx = tid + i * 128;
            int r = idx >> 4, c = (idx & 15) * 4;
            CP_ASYNC16(smb + (KS_F + r * KP + c) * 4, kbase + (size_t)r * 64 + c);
            CP_ASYNC16(smb + (VS_F + r * KP + c) * 4,
                       vbase + (size_t)r * NH * NLEN + c);
        }
        CP_COMMIT();
        CP_WAIT0();
        __syncthreads();
    }

    float o[2][8][4] = {};
    float l[2][2] = {{0.f, 0.f}, {0.f, 0.f}};
    float* Pw = sm + PS_F + wid * 32 * KP;

    for (int t = 0; t < NLEN / 64; t++) {
        const int bufc = t & 1;
        if (t + 1 < NLEN / 64) {
            const int bn = (t + 1) & 1;
            const int m0 = (t + 1) * 64;
            #pragma unroll
            for (int i = 0; i < 8; i++) {
                int idx = tid + i * 128;
                int r = idx >> 4, c = (idx & 15) * 4;
                CP_ASYNC16(smb + (KS_F + bn * 4608 + r * KP + c) * 4,
                           kbase + (size_t)(m0 + r) * 64 + c);
                CP_ASYNC16(smb + (VS_F + bn * 4608 + r * KP + c) * 4,
                           vbase + (size_t)r * NH * NLEN + m0 + c);
            }
            CP_COMMIT();
        }

        // ---- S = Q @ K^T : each kb feeds both m-frags
        const float* Ks = sm + KS_F + bufc * 4608;
        float s[2][8][4] = {};
        #pragma unroll
        for (int k = 0; k < 8; k++) {
            #pragma unroll
            for (int j = 0; j < 8; j++) {
                float2 kb = *(const float2*)&Ks[(j * 8 + gid) * KP + k * 8 + 2 * tig];
                uint32_t b0 = __float_as_uint(kb.x), b1 = __float_as_uint(kb.y);
                mma8(s[0][j], aq[0][k], b0, b1);
                mma8(s[1][j], aq[1][k], b0, b1);
            }
        }

        // ---- softmax; lsum over ROUNDED p
        #pragma unroll
        for (int f = 0; f < 2; f++)
            #pragma unroll
            for (int j = 0; j < 8; j++) {
                float p0 = f2tf32f(__expf(s[f][j][0]));
                float p1 = f2tf32f(__expf(s[f][j][1]));
                float p2 = f2tf32f(__expf(s[f][j][2]));
                float p3 = f2tf32f(__expf(s[f][j][3]));
                l[f][0] += p0 + p1;
                l[f][1] += p2 + p3;
                *(float2*)&Pw[(f * 16 + gid) * KP + j * 8 + 2 * tig] =
                    make_float2(p0, p1);
                *(float2*)&Pw[(f * 16 + gid + 8) * KP + j * 8 + 2 * tig] =
                    make_float2(p2, p3);
            }
        __syncwarp();

        // ---- O += P @ V : each vb feeds both m-frags
        const float* Vs = sm + VS_F + bufc * 4608;
        #pragma unroll
        for (int k = 0; k < 8; k++) {
            uint32_t ap[2][4];
            #pragma unroll
            for (int f = 0; f < 2; f++) {
                ap[f][0] = __float_as_uint(Pw[(f * 16 + gid) * KP + k * 8 + tig]);
                ap[f][1] = __float_as_uint(Pw[(f * 16 + gid + 8) * KP + k * 8 + tig]);
                ap[f][2] = __float_as_uint(Pw[(f * 16 + gid) * KP + k * 8 + tig + 4]);
                ap[f][3] = __float_as_uint(Pw[(f * 16 + gid + 8) * KP + k * 8 + tig + 4]);
            }
            #pragma unroll
            for (int j = 0; j < 8; j++) {
                float2 vb = *(const float2*)&Vs[(j * 8 + gid) * KP + k * 8 + 2 * tig];
                uint32_t b0 = __float_as_uint(vb.x), b1 = __float_as_uint(vb.y);
                mma8(o[0][j], ap[0], b0, b1);
                mma8(o[1][j], ap[1], b0, b1);
            }
        }
        __syncwarp();

        CP_WAIT0();
        __syncthreads();
    }

    // ---- finalize: reduce row sums across tig, normalize
    #pragma unroll
    for (int f = 0; f < 2; f++) {
        #pragma unroll
        for (int h = 0; h < 2; h++) {
            l[f][h] += __shfl_xor_sync(0xffffffffu, l[f][h], 1);
            l[f][h] += __shfl_xor_sync(0xffffffffu, l[f][h], 2);
        }
        float inv0 = 1.0f / l[f][0], inv1 = 1.0f / l[f][1];
        #pragma unroll
        for (int j = 0; j < 8; j++) {
            o[f][j][0] *= inv0; o[f][j][1] *= inv0;
            o[f][j][2] *= inv1; o[f][j][3] *= inv1;
        }
    }

    // ---- stage O as [64 d][128 q] (pitch 132), rna-round, coalesced store
    __syncthreads();
    float* stage = sm;
    #pragma unroll
    for (int f = 0; f < 2; f++) {
        int ra = wid * 32 + f * 16 + gid, rb = ra + 8;
        #pragma unroll
        for (int j = 0; j < 8; j++) {
            int d0 = j * 8 + 2 * tig;
            stage[(d0 + 0) * 132 + ra] = o[f][j][0];
            stage[(d0 + 1) * 132 + ra] = o[f][j][1];
            stage[(d0 + 0) * 132 + rb] = o[f][j][2];
            stage[(d0 + 1) * 132 + rb] = o[f][j][3];
        }
    }
    __syncthreads();
    #pragma unroll
    for (int i = 0; i < 16; i++) {
        int idx = tid + i * 128;
        int r = idx >> 5, c = (idx & 31) * 4;
        float4 t = *(const float4*)&stage[r * 132 + c];
        t.x = f2tf32f(t.x); t.y = f2tf32f(t.y);
        t.z = f2tf32f(t.z); t.w = f2tf32f(t.w);
        *(float4*)&attn[((size_t)b * DIM + r * NH + hh) * NLEN + q0 + c] = t;
    }
}

// ---------------------------------------------------------------------------
static float* symaddr(const void* sym) {
    void* p = nullptr;
    cudaGetSymbolAddress(&p, sym);
    return (float*)p;
}

extern "C" void kernel_launch(void* const* d_in, const int* in_sizes, int n_in,
                              void* d_out, int out_size)
{
    const float* x      = (const float*)d_in[0];
    const float* source = (const float*)d_in[1];
    const float* Wq = (const float*)d_in[2];
    const float* bq = (const float*)d_in[3];
    const float* Wk = (const float*)d_in[4];
    const float* bk = (const float*)d_in[5];
    const float* Wv = (const float*)d_in[6];
    const float* bv = (const float*)d_in[7];
    const float* Wo = (const float*)d_in[8];
    const float* bo = (const float*)d_in[9];
    const float* W1 = (const float*)d_in[10];
    const float* b1 = (const float*)d_in[11];
    const float* gamma = (const float*)d_in[12];
    const float* beta  = (const float*)d_in[13];
    const float* W2 = (const float*)d_in[14];
    const float* b2 = (const float*)d_in[15];
    float* out = (float*)d_out;

    float* q    = symaddr(g_q);
    float* kbuf = symaddr(g_k);
    float* vbuf = symaddr(g_v);
    float* attn = symaddr(g_attn);
    float* msg  = symaddr(g_msg);
    float* hbuf = symaddr(g_h);
    float* scl  = symaddr(g_scale);
    float* shf  = symaddr(g_shift);
    float* wr   = symaddr(g_wr);

    cudaFuncSetAttribute(flash_mma,
                         cudaFuncAttributeMaxDynamicSharedMemorySize, FLASH_SMEM);
    cudaFuncSetAttribute(gemm_qkv,
                         cudaFuncAttributeMaxDynamicSharedMemorySize, GEMM_SMEM);
    cudaFuncSetAttribute(gemm_ms<0>,
                         cudaFuncAttributeMaxDynamicSharedMemorySize, GEMM_SMEM);
    cudaFuncSetAttribute(gemm_ms<3>,
                         cudaFuncAttributeMaxDynamicSharedMemorySize, GEMM_SMEM);
    cudaFuncSetAttribute(gemm_bn64,
                         cudaFuncAttributeMaxDynamicSharedMemorySize, BN64_SMEM);

    dim3 blk(256);
    // weights -> tf32 (rna)
    round_weights<<<2560, blk>>>(Wq, Wk, Wv, Wo, W1, W2, wr);
    // fused Q/K/V projections
    gemm_qkv<<<dim3(32, 2, 6), blk, GEMM_SMEM>>>(
        wr, bq, bk, bv, x, source, q, kbuf, vbuf);
    // attention (v2: 128 threads, 32 rows/warp)
    flash_mma<<<dim3(32, NH, NB), dim3(128), FLASH_SMEM>>>(q, kbuf, vbuf, attn);
    // output projection (rounds output)
    gemm_ms<0><<<dim3(32, 2, 2), blk, GEMM_SMEM>>>(
        wr + WR_O, bo, attn, nullptr, msg);
    // MLP layer 1 over concat([x, msg])
    gemm_ms<3><<<dim3(32, 4, 2), blk, GEMM_SMEM>>>(
        wr + WR_1, b1, x, msg, hbuf);
    // batchnorm stats -> per-channel scale/shift
    bn_stats<<<512, blk>>>(hbuf, gamma, beta, scl, shf);
    // MLP layer 2 with fused normalize+relu (final output, 64-wide N tiles)
    gemm_bn64<<<dim3(128, 2), blk, BN64_SMEM>>>(
        wr + WR_2, b2, hbuf, scl, shf, out);
}